// round 1
// baseline (speedup 1.0000x reference)
#include <cuda_runtime.h>
#include <cstdint>
#include <cstddef>

#define S_LEN 4096
#define DHEAD 64
#define N_BH  16
#define BQ    64
#define BK    64
// 1/sqrt(64) * log2(e)
#define SCALE_LOG2E 0.18033688011112042f

// Packed mask bits: bit=1 means "keep" (mask true). 4096*4096/32 words = 2MB.
__device__ uint32_t g_mask_bits[(S_LEN * S_LEN) / 32];
__device__ int g_mask_wide;

// ---------------------------------------------------------------------------
// Detect whether the boolean mask was serialized as 4-byte words (int32/float32
// 0/1) or as 1-byte values. With random 0/1 bytes, a 32-bit word is almost
// never in {0, 1, 0x3F800000}; with word-serialized bools it always is.
// ---------------------------------------------------------------------------
__global__ void detect_mask_kernel(const uint32_t* __restrict__ m) {
    bool wide = true;
    for (int i = threadIdx.x; i < 1024; i += 32) {
        uint32_t w = m[i];
        if (w != 0u && w != 1u && w != 0x3F800000u) wide = false;
    }
    wide = __all_sync(0xffffffffu, wide);
    if (threadIdx.x == 0) g_mask_wide = wide ? 1 : 0;
}

// ---------------------------------------------------------------------------
// Pack mask into bitmask. One thread per mask element; ballot -> 1 word/warp.
// ---------------------------------------------------------------------------
__global__ void pack_mask_kernel(const void* __restrict__ mask) {
    int idx = blockIdx.x * blockDim.x + threadIdx.x;
    bool v;
    if (g_mask_wide) {
        v = (((const uint32_t*)mask)[idx] != 0u);
    } else {
        v = (((const uint8_t*)mask)[idx] != 0);
    }
    uint32_t bits = __ballot_sync(0xffffffffu, v);
    if ((threadIdx.x & 31) == 0) g_mask_bits[idx >> 5] = bits;
}

// ---------------------------------------------------------------------------
// FP32 SIMT flash attention.
// Grid: (S/BQ, B*H). Block: 256 threads = 16x16, each thread owns a 4x4
// micro-tile of scores and a 4x4 micro-tile of O (same 4 q-rows).
// Shared: Qs,Ks d-major [64][68] (float4-aligned pad), Ps k-major [64][68],
// Vs [64][64] direct copy (gmem layout already k-major over d).
// ---------------------------------------------------------------------------
__global__ void __launch_bounds__(256)
attn_kernel(const float* __restrict__ Q, const float* __restrict__ K,
            const float* __restrict__ V, float* __restrict__ Out) {
    extern __shared__ float sm[];
    float* Qs = sm;                 // [64][68], Qs[d*68+q]
    float* Ks = Qs + 64 * 68;       // [64][68], Ks[d*68+k]
    float* Ps = Ks + 64 * 68;       // [64][68], Ps[k*68+q]
    float* Vs = Ps + 64 * 68;       // [64][64], Vs[k*64+d]

    const int tid = threadIdx.x;
    const int tx = tid & 15;        // k / d sub-tile
    const int ty = tid >> 4;        // q sub-tile
    const int qbase = blockIdx.x * BQ;
    const int bh = blockIdx.y;

    const float* Qg = Q + ((size_t)bh * S_LEN + qbase) * DHEAD;
    const float* Kg = K + (size_t)bh * S_LEN * DHEAD;
    const float* Vg = V + (size_t)bh * S_LEN * DHEAD;

    // Load Q tile transposed into Qs (once per CTA).
#pragma unroll
    for (int it = 0; it < 4; it++) {
        int fid = it * 256 + tid;       // 0..1023 float4s
        int q   = fid >> 4;             // 0..63
        int d4  = (fid & 15) << 2;      // 0..60
        float4 v = *(const float4*)(Qg + q * DHEAD + d4);
        Qs[(d4 + 0) * 68 + q] = v.x;
        Qs[(d4 + 1) * 68 + q] = v.y;
        Qs[(d4 + 2) * 68 + q] = v.z;
        Qs[(d4 + 3) * 68 + q] = v.w;
    }

    float Oa[4][4];
    float m[4], l[4];
#pragma unroll
    for (int i = 0; i < 4; i++) {
        m[i] = -1e30f;
        l[i] = 0.0f;
#pragma unroll
        for (int j = 0; j < 4; j++) Oa[i][j] = 0.0f;
    }

    for (int kt = 0; kt < S_LEN / BK; kt++) {
        const int kbase = kt * BK;
        __syncthreads();  // previous PV done reading Ks/Vs/Ps

        // Load K transposed, V direct.
#pragma unroll
        for (int it = 0; it < 4; it++) {
            int fid = it * 256 + tid;
            int r   = fid >> 4;
            int d4  = (fid & 15) << 2;
            float4 kv = *(const float4*)(Kg + (size_t)(kbase + r) * DHEAD + d4);
            Ks[(d4 + 0) * 68 + r] = kv.x;
            Ks[(d4 + 1) * 68 + r] = kv.y;
            Ks[(d4 + 2) * 68 + r] = kv.z;
            Ks[(d4 + 3) * 68 + r] = kv.w;
            float4 vv = *(const float4*)(Vg + (size_t)(kbase + r) * DHEAD + d4);
            *(float4*)&Vs[r * 64 + d4] = vv;
        }
        __syncthreads();

        // S = Q K^T over d
        float acc[4][4];
#pragma unroll
        for (int i = 0; i < 4; i++)
#pragma unroll
            for (int j = 0; j < 4; j++) acc[i][j] = 0.0f;

#pragma unroll 8
        for (int d = 0; d < 64; d++) {
            float4 qv = *(const float4*)&Qs[d * 68 + ty * 4];
            float4 kv = *(const float4*)&Ks[d * 68 + tx * 4];
            float qa[4] = {qv.x, qv.y, qv.z, qv.w};
            float ka[4] = {kv.x, kv.y, kv.z, kv.w};
#pragma unroll
            for (int i = 0; i < 4; i++)
#pragma unroll
                for (int j = 0; j < 4; j++) acc[i][j] = fmaf(qa[i], ka[j], acc[i][j]);
        }

        // Masked online softmax (base-2 domain).
        float oal[4];
        const int sh = (tx * 4) & 31;
#pragma unroll
        for (int i = 0; i < 4; i++) {
            int row = qbase + ty * 4 + i;
            uint32_t w = g_mask_bits[(row << 7) + (kbase >> 5) + (tx >> 3)];
            float tm = -1e30f;
#pragma unroll
            for (int j = 0; j < 4; j++) {
                float s = acc[i][j] * SCALE_LOG2E;
                if (!((w >> (sh + j)) & 1u)) s = -1e30f;
                acc[i][j] = s;
                tm = fmaxf(tm, s);
            }
            tm = fmaxf(tm, __shfl_xor_sync(0xffffffffu, tm, 1));
            tm = fmaxf(tm, __shfl_xor_sync(0xffffffffu, tm, 2));
            tm = fmaxf(tm, __shfl_xor_sync(0xffffffffu, tm, 4));
            tm = fmaxf(tm, __shfl_xor_sync(0xffffffffu, tm, 8));
            float mn = fmaxf(m[i], tm);
            float al = exp2f(m[i] - mn);
            m[i] = mn;
            oal[i] = al;
            float rs = 0.0f;
#pragma unroll
            for (int j = 0; j < 4; j++) {
                float p = (acc[i][j] > -1e29f) ? exp2f(acc[i][j] - mn) : 0.0f;
                acc[i][j] = p;
                rs += p;
            }
            rs += __shfl_xor_sync(0xffffffffu, rs, 1);
            rs += __shfl_xor_sync(0xffffffffu, rs, 2);
            rs += __shfl_xor_sync(0xffffffffu, rs, 4);
            rs += __shfl_xor_sync(0xffffffffu, rs, 8);
            l[i] = l[i] * al + rs;
        }

        // Stage P into smem k-major.
#pragma unroll
        for (int j = 0; j < 4; j++)
#pragma unroll
            for (int i = 0; i < 4; i++)
                Ps[(tx * 4 + j) * 68 + (ty * 4 + i)] = acc[i][j];
        __syncthreads();

        // Rescale O and accumulate P V.
#pragma unroll
        for (int i = 0; i < 4; i++)
#pragma unroll
            for (int j = 0; j < 4; j++) Oa[i][j] *= oal[i];

#pragma unroll 8
        for (int k = 0; k < 64; k++) {
            float4 pv = *(const float4*)&Ps[k * 68 + ty * 4];
            float4 vv = *(const float4*)&Vs[k * 64 + tx * 4];
            float pa[4] = {pv.x, pv.y, pv.z, pv.w};
            float va[4] = {vv.x, vv.y, vv.z, vv.w};
#pragma unroll
            for (int i = 0; i < 4; i++)
#pragma unroll
                for (int j = 0; j < 4; j++) Oa[i][j] = fmaf(pa[i], va[j], Oa[i][j]);
        }
    }

    // Epilogue: normalize and store.
#pragma unroll
    for (int i = 0; i < 4; i++) {
        float inv = (l[i] > 0.0f) ? (1.0f / l[i]) : 0.0f;
        float4 o;
        o.x = Oa[i][0] * inv;
        o.y = Oa[i][1] * inv;
        o.z = Oa[i][2] * inv;
        o.w = Oa[i][3] * inv;
        size_t row = (size_t)bh * S_LEN + qbase + ty * 4 + i;
        *(float4*)(Out + row * DHEAD + tx * 4) = o;
    }
}

extern "C" void kernel_launch(void* const* d_in, const int* in_sizes, int n_in,
                              void* d_out, int out_size) {
    const float* Q = (const float*)d_in[0];
    const float* K = (const float*)d_in[1];
    const float* V = (const float*)d_in[2];
    // d_in[3] = d_k (unused, D=64 compile-time)
    const void* mask = d_in[4];
    float* Out = (float*)d_out;

    detect_mask_kernel<<<1, 32>>>((const uint32_t*)mask);
    pack_mask_kernel<<<(S_LEN * S_LEN) / 256, 256>>>(mask);

    size_t smem = (size_t)(64 * 68 * 3 + 64 * 64) * sizeof(float);  // 68608 B
    cudaFuncSetAttribute(attn_kernel, cudaFuncAttributeMaxDynamicSharedMemorySize,
                         (int)smem);
    attn_kernel<<<dim3(S_LEN / BQ, N_BH), 256, smem>>>(Q, K, V, Out);
}

// round 3
// speedup vs baseline: 3.0204x; 3.0204x over previous
#include <cuda_runtime.h>
#include <cuda_bf16.h>
#include <cstdint>
#include <cstddef>

#define S_LEN 4096
#define DHEAD 64
#define N_BH  16
#define BQ    128
#define BK    64
#define NT    (S_LEN / BK)
// 1/sqrt(64) * log2(e)
#define SCALE_LOG2E 0.18033688011112042f

// ---------------- scratch (device globals; no runtime alloc) ----------------
__device__ __nv_bfloat16 g_qh[(size_t)N_BH * S_LEN * DHEAD];
__device__ __nv_bfloat16 g_ql[(size_t)N_BH * S_LEN * DHEAD];
__device__ __nv_bfloat16 g_kh[(size_t)N_BH * S_LEN * DHEAD];
__device__ __nv_bfloat16 g_kl[(size_t)N_BH * S_LEN * DHEAD];
__device__ __nv_bfloat16 g_vh[(size_t)N_BH * S_LEN * DHEAD];
__device__ __nv_bfloat16 g_vl[(size_t)N_BH * S_LEN * DHEAD];
__device__ uint32_t g_mask_bits[(S_LEN * S_LEN) / 32];
__device__ int g_mask_wide;

// ---------------- smem layout (bytes) ----------------
// Q hi [128x64 bf16 = 16KB], Q lo, then 2 stages of {KH,KL,VH,VL} 8KB each.
#define QH_OFF 0
#define QL_OFF 16384
#define STAGE_OFF(s) (32768 + (s) * 32768)
#define KH_OFF 0
#define KL_OFF 8192
#define VH_OFF 16384
#define VL_OFF 24576
#define SMEM_BYTES 98304

// swizzled byte offset of (row, 16B-chunk) in a 128B-row tile
__device__ __forceinline__ uint32_t swz(int row, int chunk) {
    return (uint32_t)(row * 128 + ((chunk ^ (row & 7)) << 4));
}

// ---------------- PTX helpers ----------------
__device__ __forceinline__ uint32_t s2u(const void* p) {
    uint32_t a;
    asm("{ .reg .u64 t; cvta.to.shared.u64 t, %1; cvt.u32.u64 %0, t; }" : "=r"(a) : "l"(p));
    return a;
}
__device__ __forceinline__ float ex2f(float x) {
    float y;
    asm("ex2.approx.ftz.f32 %0, %1;" : "=f"(y) : "f"(x));
    return y;
}
__device__ __forceinline__ void ldsm4(uint32_t* r, uint32_t addr) {
    asm volatile("ldmatrix.sync.aligned.m8n8.x4.shared.b16 {%0, %1, %2, %3}, [%4];"
                 : "=r"(r[0]), "=r"(r[1]), "=r"(r[2]), "=r"(r[3]) : "r"(addr));
}
__device__ __forceinline__ void ldsm4t(uint32_t* r, uint32_t addr) {
    asm volatile("ldmatrix.sync.aligned.m8n8.x4.trans.shared.b16 {%0, %1, %2, %3}, [%4];"
                 : "=r"(r[0]), "=r"(r[1]), "=r"(r[2]), "=r"(r[3]) : "r"(addr));
}
__device__ __forceinline__ void mma16816(float* d, const uint32_t* a, uint32_t b0, uint32_t b1) {
    asm volatile("mma.sync.aligned.m16n8k16.row.col.f32.bf16.bf16.f32 "
                 "{%0, %1, %2, %3}, {%4, %5, %6, %7}, {%8, %9}, {%0, %1, %2, %3};"
                 : "+f"(d[0]), "+f"(d[1]), "+f"(d[2]), "+f"(d[3])
                 : "r"(a[0]), "r"(a[1]), "r"(a[2]), "r"(a[3]), "r"(b0), "r"(b1));
}
__device__ __forceinline__ void cpa16(uint32_t dst, const void* src) {
    asm volatile("cp.async.cg.shared.global [%0], [%1], 16;" :: "r"(dst), "l"(src));
}
#define CPA_COMMIT() asm volatile("cp.async.commit_group;" ::: "memory")
#define CPA_WAIT0()  asm volatile("cp.async.wait_group 0;" ::: "memory")

// ---------------- preprocess kernels ----------------
__global__ void detect_mask_kernel(const uint32_t* __restrict__ m) {
    bool wide = true;
    for (int i = threadIdx.x; i < 1024; i += 32) {
        uint32_t w = m[i];
        if (w != 0u && w != 1u && w != 0x3F800000u) wide = false;
    }
    wide = __all_sync(0xffffffffu, wide);
    if (threadIdx.x == 0) g_mask_wide = wide ? 1 : 0;
}

__global__ void pack_mask_kernel(const void* __restrict__ mask) {
    int idx = blockIdx.x * blockDim.x + threadIdx.x;
    bool v;
    if (g_mask_wide) v = (((const uint32_t*)mask)[idx] != 0u);
    else             v = (((const uint8_t*)mask)[idx] != 0);
    uint32_t bits = __ballot_sync(0xffffffffu, v);
    if ((threadIdx.x & 31) == 0) g_mask_bits[idx >> 5] = bits;
}

__global__ void split_qk_kernel(const float* __restrict__ Q, const float* __restrict__ K) {
    size_t idx = (size_t)blockIdx.x * 256 + threadIdx.x;
    float q = Q[idx] * SCALE_LOG2E;
    __nv_bfloat16 qh = __float2bfloat16(q);
    g_qh[idx] = qh;
    g_ql[idx] = __float2bfloat16(q - __bfloat162float(qh));
    float k = K[idx];
    __nv_bfloat16 kh = __float2bfloat16(k);
    g_kh[idx] = kh;
    g_kl[idx] = __float2bfloat16(k - __bfloat162float(kh));
}

__global__ void split_v_kernel(const float* __restrict__ V) {
    size_t idx = (size_t)blockIdx.x * 256 + threadIdx.x;
    float v = V[idx];
    __nv_bfloat16 vh = __float2bfloat16(v);
    g_vh[idx] = vh;
    g_vl[idx] = __float2bfloat16(v - __bfloat162float(vh));
}

// ---------------- tile loaders ----------------
// K/V tiles: 64 rows x 64 bf16 = 128B/row, hi+lo x K,V into one stage.
__device__ __forceinline__ void load_kv(uint32_t sb, int stage, size_t ebase, int tid) {
    uint32_t base = sb + STAGE_OFF(stage);
#pragma unroll
    for (int it = 0; it < 2; it++) {
        int cid = it * 256 + tid;            // 0..511 chunks
        int row = cid >> 3, c = cid & 7;
        uint32_t off = swz(row, c);
        size_t src = ebase + (size_t)row * DHEAD + c * 8;
        cpa16(base + KH_OFF + off, g_kh + src);
        cpa16(base + KL_OFF + off, g_kl + src);
        cpa16(base + VH_OFF + off, g_vh + src);
        cpa16(base + VL_OFF + off, g_vl + src);
    }
}
// Q tile: 128 rows x 64 bf16, hi+lo.
__device__ __forceinline__ void load_q(uint32_t sb, size_t ebase, int tid) {
#pragma unroll
    for (int it = 0; it < 4; it++) {
        int cid = it * 256 + tid;            // 0..1023
        int row = cid >> 3, c = cid & 7;
        uint32_t off = swz(row, c);
        size_t src = ebase + (size_t)row * DHEAD + c * 8;
        cpa16(sb + QH_OFF + off, g_qh + src);
        cpa16(sb + QL_OFF + off, g_ql + src);
    }
}

// ---------------- main attention kernel ----------------
__global__ void __launch_bounds__(256, 1)
attn_hmma_kernel(float* __restrict__ Out) {
    extern __shared__ char smem[];
    uint32_t sb = s2u(smem);
    const int tid = threadIdx.x;
    const int w = tid >> 5, l = tid & 31;
    const int bh = blockIdx.y;
    const int qbase = blockIdx.x * BQ;

    // ldmatrix lane template: row-part and chunk-part
    const int lrow = (l & 7) + ((l & 8) ? 8 : 0);     // 0..15
    const int lch  = (l & 16) ? 1 : 0;

    load_q(sb, ((size_t)bh * S_LEN + qbase) * DHEAD, tid);
    load_kv(sb, 0, ((size_t)bh * S_LEN) * DHEAD, tid);
    CPA_COMMIT();
    CPA_WAIT0();
    __syncthreads();

    // Q fragments (held in registers for all iterations)
    uint32_t qh[4][4], ql[4][4];
    {
        const int qrow = w * 16 + lrow;
#pragma unroll
        for (int kb = 0; kb < 4; kb++) {
            uint32_t off = swz(qrow, kb * 2 + lch);
            ldsm4(qh[kb], sb + QH_OFF + off);
            ldsm4(ql[kb], sb + QL_OFF + off);
        }
    }

    float o[8][4];
#pragma unroll
    for (int nb = 0; nb < 8; nb++)
#pragma unroll
        for (int j = 0; j < 4; j++) o[nb][j] = 0.0f;
    float m0 = -1e30f, m1 = -1e30f, l0 = 0.0f, l1 = 0.0f;

    const uint32_t* mask_row0 =
        g_mask_bits + ((size_t)(qbase + w * 16 + (l >> 2))) * (S_LEN / 32);

    for (int t = 0; t < NT; t++) {
        const int st = t & 1;
        const uint32_t kbuf = sb + STAGE_OFF(st);

        if (t + 1 < NT)
            load_kv(sb, st ^ 1, ((size_t)bh * S_LEN + (t + 1) * BK) * DHEAD, tid);
        CPA_COMMIT();

        // ---- S = Q K^T (3-term split) ----
        float s[8][4];
#pragma unroll
        for (int nb = 0; nb < 8; nb++)
#pragma unroll
            for (int j = 0; j < 4; j++) s[nb][j] = 0.0f;

#pragma unroll
        for (int kb = 0; kb < 4; kb++) {
#pragma unroll
            for (int nbp = 0; nbp < 4; nbp++) {
                uint32_t off = swz(nbp * 16 + lrow, kb * 2 + lch);
                uint32_t kh[4], kl[4];
                ldsm4(kh, kbuf + KH_OFF + off);
                ldsm4(kl, kbuf + KL_OFF + off);
                // K frag pairing: nb even -> {r0,r2}; nb odd -> {r1,r3}
                mma16816(s[nbp * 2],     qh[kb], kh[0], kh[2]);
                mma16816(s[nbp * 2],     qh[kb], kl[0], kl[2]);
                mma16816(s[nbp * 2],     ql[kb], kh[0], kh[2]);
                mma16816(s[nbp * 2 + 1], qh[kb], kh[1], kh[3]);
                mma16816(s[nbp * 2 + 1], qh[kb], kl[1], kl[3]);
                mma16816(s[nbp * 2 + 1], ql[kb], kh[1], kh[3]);
            }
        }

        // ---- masked online softmax (rows are warp-private) ----
        const uint2 ma = *(const uint2*)(mask_row0 + (t * BK >> 5));
        const uint2 mb = *(const uint2*)(mask_row0 + 8 * (S_LEN / 32) + (t * BK >> 5));
        const int j0 = (l & 3) * 2;
        float mx0 = -1e30f, mx1 = -1e30f;
#pragma unroll
        for (int nb = 0; nb < 8; nb++) {
            int c0 = nb * 8 + j0, c1 = c0 + 1;
            uint32_t wa0 = (c0 & 32) ? ma.y : ma.x;
            uint32_t wb0 = (c0 & 32) ? mb.y : mb.x;
            if (!((wa0 >> (c0 & 31)) & 1u)) s[nb][0] = -1e30f;
            if (!((wa0 >> (c1 & 31)) & 1u)) s[nb][1] = -1e30f;
            if (!((wb0 >> (c0 & 31)) & 1u)) s[nb][2] = -1e30f;
            if (!((wb0 >> (c1 & 31)) & 1u)) s[nb][3] = -1e30f;
            mx0 = fmaxf(mx0, fmaxf(s[nb][0], s[nb][1]));
            mx1 = fmaxf(mx1, fmaxf(s[nb][2], s[nb][3]));
        }
        mx0 = fmaxf(mx0, __shfl_xor_sync(0xffffffffu, mx0, 1));
        mx0 = fmaxf(mx0, __shfl_xor_sync(0xffffffffu, mx0, 2));
        mx1 = fmaxf(mx1, __shfl_xor_sync(0xffffffffu, mx1, 1));
        mx1 = fmaxf(mx1, __shfl_xor_sync(0xffffffffu, mx1, 2));
        float mn0 = fmaxf(m0, mx0), mn1 = fmaxf(m1, mx1);
        float al0 = ex2f(m0 - mn0), al1 = ex2f(m1 - mn1);
        m0 = mn0; m1 = mn1;

        float rs0 = 0.0f, rs1 = 0.0f;
        uint32_t ph[4][4], pl[4][4];
#pragma unroll
        for (int nb = 0; nb < 8; nb++) {
            float p0 = (s[nb][0] > -1e29f) ? ex2f(s[nb][0] - mn0) : 0.0f;
            float p1 = (s[nb][1] > -1e29f) ? ex2f(s[nb][1] - mn0) : 0.0f;
            float p2 = (s[nb][2] > -1e29f) ? ex2f(s[nb][2] - mn1) : 0.0f;
            float p3 = (s[nb][3] > -1e29f) ? ex2f(s[nb][3] - mn1) : 0.0f;
            rs0 += p0 + p1;
            rs1 += p2 + p3;
            __nv_bfloat162 h01 = __floats2bfloat162_rn(p0, p1);
            __nv_bfloat162 h23 = __floats2bfloat162_rn(p2, p3);
            __nv_bfloat162 l01 = __floats2bfloat162_rn(p0 - __bfloat162float(h01.x),
                                                       p1 - __bfloat162float(h01.y));
            __nv_bfloat162 l23 = __floats2bfloat162_rn(p2 - __bfloat162float(h23.x),
                                                       p3 - __bfloat162float(h23.y));
            int pk = nb >> 1, hi = (nb & 1) * 1;
            // A-frag order: a0=(i,klow), a1=(i+8,klow), a2=(i,khigh), a3=(i+8,khigh)
            // nb even -> klow (regs 0,1); nb odd -> khigh (regs 2,3)
            ph[pk][hi * 2 + 0] = *(uint32_t*)&h01;
            ph[pk][hi * 2 + 1] = *(uint32_t*)&h23;
            pl[pk][hi * 2 + 0] = *(uint32_t*)&l01;
            pl[pk][hi * 2 + 1] = *(uint32_t*)&l23;
        }
        rs0 += __shfl_xor_sync(0xffffffffu, rs0, 1);
        rs0 += __shfl_xor_sync(0xffffffffu, rs0, 2);
        rs1 += __shfl_xor_sync(0xffffffffu, rs1, 1);
        rs1 += __shfl_xor_sync(0xffffffffu, rs1, 2);
        l0 = l0 * al0 + rs0;
        l1 = l1 * al1 + rs1;

        // rescale O
#pragma unroll
        for (int nb = 0; nb < 8; nb++) {
            o[nb][0] *= al0; o[nb][1] *= al0;
            o[nb][2] *= al1; o[nb][3] *= al1;
        }

        // ---- O += P V (3-term split) ----
#pragma unroll
        for (int pk = 0; pk < 4; pk++) {
#pragma unroll
            for (int nbp = 0; nbp < 4; nbp++) {
                uint32_t off = swz(pk * 16 + lrow, nbp * 2 + lch);
                uint32_t vh[4], vl[4];
                ldsm4t(vh, kbuf + VH_OFF + off);
                ldsm4t(vl, kbuf + VL_OFF + off);
                // V frag pairing: nb even -> {r0,r1}; nb odd -> {r2,r3}
                mma16816(o[nbp * 2],     ph[pk], vh[0], vh[1]);
                mma16816(o[nbp * 2],     ph[pk], vl[0], vl[1]);
                mma16816(o[nbp * 2],     pl[pk], vh[0], vh[1]);
                mma16816(o[nbp * 2 + 1], ph[pk], vh[2], vh[3]);
                mma16816(o[nbp * 2 + 1], ph[pk], vl[2], vl[3]);
                mma16816(o[nbp * 2 + 1], pl[pk], vh[2], vh[3]);
            }
        }

        CPA_WAIT0();
        __syncthreads();
    }

    // ---- epilogue ----
    float inv0 = (l0 > 0.0f) ? (1.0f / l0) : 0.0f;
    float inv1 = (l1 > 0.0f) ? (1.0f / l1) : 0.0f;
    const int r0g = qbase + w * 16 + (l >> 2);
    float* op = Out + ((size_t)bh * S_LEN + r0g) * DHEAD + (l & 3) * 2;
#pragma unroll
    for (int nb = 0; nb < 8; nb++) {
        float2 v0 = make_float2(o[nb][0] * inv0, o[nb][1] * inv0);
        float2 v1 = make_float2(o[nb][2] * inv1, o[nb][3] * inv1);
        *(float2*)(op + nb * 8) = v0;
        *(float2*)(op + 8 * DHEAD + nb * 8) = v1;
    }
}

// ---------------- launch ----------------
extern "C" void kernel_launch(void* const* d_in, const int* in_sizes, int n_in,
                              void* d_out, int out_size) {
    const float* Q = (const float*)d_in[0];
    const float* K = (const float*)d_in[1];
    const float* V = (const float*)d_in[2];
    const void* mask = d_in[4];
    float* Out = (float*)d_out;

    detect_mask_kernel<<<1, 32>>>((const uint32_t*)mask);
    pack_mask_kernel<<<(S_LEN * S_LEN) / 256, 256>>>(mask);
    split_qk_kernel<<<(N_BH * S_LEN * DHEAD) / 256, 256>>>(Q, K);
    split_v_kernel<<<(N_BH * S_LEN * DHEAD) / 256, 256>>>(V);

    cudaFuncSetAttribute(attn_hmma_kernel, cudaFuncAttributeMaxDynamicSharedMemorySize,
                         SMEM_BYTES);
    attn_hmma_kernel<<<dim3(S_LEN / BQ, N_BH), 256, SMEM_BYTES>>>(Out);
}

// round 4
// speedup vs baseline: 5.0487x; 1.6715x over previous
#include <cuda_runtime.h>
#include <cuda_fp16.h>
#include <cstdint>
#include <cstddef>

#define S_LEN 4096
#define DHEAD 64
#define N_BH  16
#define BQ    64
#define BK    64
#define NTU   32              // k-tiles per unit (half the sequence)
// 1/sqrt(64) * log2(e)
#define SCALE_LOG2E 0.18033688011112042f

// ---------------- scratch (device globals; no runtime alloc) ----------------
__device__ __half g_qh[(size_t)N_BH * S_LEN * DHEAD];
__device__ __half g_ql[(size_t)N_BH * S_LEN * DHEAD];
__device__ __half g_kh[(size_t)N_BH * S_LEN * DHEAD];
__device__ __half g_vh[(size_t)N_BH * S_LEN * DHEAD];
__device__ __half g_vl[(size_t)N_BH * S_LEN * DHEAD];
__device__ float  g_U[(size_t)N_BH * 2 * S_LEN * DHEAD];   // unnormalized partial O
__device__ float2 g_ml[(size_t)N_BH * 2 * S_LEN];          // (m, l) per partial row
__device__ uint32_t g_mask_bits[(S_LEN * S_LEN) / 32];
__device__ int g_mask_wide;

// ---------------- smem layout (bytes) ----------------
// Qh[64x64 fp16 = 8KB], Ql[8KB], 2 stages of {Kh 8KB, Vh 8KB, Vl 8KB}.
#define QH_OFF 0
#define QL_OFF 8192
#define STAGE_OFF(s) (16384 + (s) * 24576)
#define KH_OFF 0
#define VH_OFF 8192
#define VL_OFF 16384
#define SMEM_BYTES 65536

// swizzled byte offset of (row, 16B-chunk) in a 128B-row tile
__device__ __forceinline__ uint32_t swz(int row, int chunk) {
    return (uint32_t)(row * 128 + ((chunk ^ (row & 7)) << 4));
}

// ---------------- PTX helpers ----------------
__device__ __forceinline__ uint32_t s2u(const void* p) {
    uint32_t a;
    asm("{ .reg .u64 t; cvta.to.shared.u64 t, %1; cvt.u32.u64 %0, t; }" : "=r"(a) : "l"(p));
    return a;
}
__device__ __forceinline__ float ex2f(float x) {
    float y;
    asm("ex2.approx.ftz.f32 %0, %1;" : "=f"(y) : "f"(x));
    return y;
}
__device__ __forceinline__ void ldsm4(uint32_t* r, uint32_t addr) {
    asm volatile("ldmatrix.sync.aligned.m8n8.x4.shared.b16 {%0, %1, %2, %3}, [%4];"
                 : "=r"(r[0]), "=r"(r[1]), "=r"(r[2]), "=r"(r[3]) : "r"(addr));
}
__device__ __forceinline__ void ldsm4t(uint32_t* r, uint32_t addr) {
    asm volatile("ldmatrix.sync.aligned.m8n8.x4.trans.shared.b16 {%0, %1, %2, %3}, [%4];"
                 : "=r"(r[0]), "=r"(r[1]), "=r"(r[2]), "=r"(r[3]) : "r"(addr));
}
__device__ __forceinline__ void mma16816(float* d, const uint32_t* a, uint32_t b0, uint32_t b1) {
    asm volatile("mma.sync.aligned.m16n8k16.row.col.f32.f16.f16.f32 "
                 "{%0, %1, %2, %3}, {%4, %5, %6, %7}, {%8, %9}, {%0, %1, %2, %3};"
                 : "+f"(d[0]), "+f"(d[1]), "+f"(d[2]), "+f"(d[3])
                 : "r"(a[0]), "r"(a[1]), "r"(a[2]), "r"(a[3]), "r"(b0), "r"(b1));
}
__device__ __forceinline__ void cpa16(uint32_t dst, const void* src) {
    asm volatile("cp.async.cg.shared.global [%0], [%1], 16;" :: "r"(dst), "l"(src));
}
#define CPA_COMMIT() asm volatile("cp.async.commit_group;" ::: "memory")
#define CPA_WAIT0()  asm volatile("cp.async.wait_group 0;" ::: "memory")

// ---------------- preprocess kernels ----------------
__global__ void detect_mask_kernel(const uint32_t* __restrict__ m) {
    bool wide = true;
    for (int i = threadIdx.x; i < 1024; i += 32) {
        uint32_t w = m[i];
        if (w != 0u && w != 1u && w != 0x3F800000u) wide = false;
    }
    wide = __all_sync(0xffffffffu, wide);
    if (threadIdx.x == 0) g_mask_wide = wide ? 1 : 0;
}

__global__ void pack_mask_kernel(const void* __restrict__ mask) {
    int idx = blockIdx.x * blockDim.x + threadIdx.x;
    bool v;
    if (g_mask_wide) v = (((const uint32_t*)mask)[idx] != 0u);
    else             v = (((const uint8_t*)mask)[idx] != 0);
    uint32_t bits = __ballot_sync(0xffffffffu, v);
    if ((threadIdx.x & 31) == 0) g_mask_bits[idx >> 5] = bits;
}

__global__ void split_kernel(const float* __restrict__ Q, const float* __restrict__ K,
                             const float* __restrict__ V) {
    size_t idx = (size_t)blockIdx.x * 256 + threadIdx.x;
    float q = Q[idx] * SCALE_LOG2E;
    __half qh = __float2half_rn(q);
    g_qh[idx] = qh;
    g_ql[idx] = __float2half_rn(q - __half2float(qh));
    g_kh[idx] = __float2half_rn(K[idx]);
    float v = V[idx];
    __half vh = __float2half_rn(v);
    g_vh[idx] = vh;
    g_vl[idx] = __float2half_rn(v - __half2float(vh));
}

// ---------------- tile loaders ----------------
__device__ __forceinline__ void load_kv(uint32_t sb, int stage, size_t ebase, int tid) {
    uint32_t base = sb + STAGE_OFF(stage);
#pragma unroll
    for (int it = 0; it < 4; it++) {
        int cid = it * 128 + tid;            // 0..511 chunks, 64 rows x 8 chunks
        int row = cid >> 3, c = cid & 7;
        uint32_t off = swz(row, c);
        size_t src = ebase + (size_t)row * DHEAD + c * 8;
        cpa16(base + KH_OFF + off, g_kh + src);
        cpa16(base + VH_OFF + off, g_vh + src);
        cpa16(base + VL_OFF + off, g_vl + src);
    }
}
__device__ __forceinline__ void load_q(uint32_t sb, size_t ebase, int tid) {
#pragma unroll
    for (int it = 0; it < 4; it++) {
        int cid = it * 128 + tid;
        int row = cid >> 3, c = cid & 7;
        uint32_t off = swz(row, c);
        size_t src = ebase + (size_t)row * DHEAD + c * 8;
        cpa16(sb + QH_OFF + off, g_qh + src);
        cpa16(sb + QL_OFF + off, g_ql + src);
    }
}

// ---------------- main attention kernel ----------------
// Unit = (bh, qtile of 64 rows, kv-half of 2048 keys). 128 threads, 4 warps,
// each warp owns 16 q-rows x all 64 keys of the tile.
__global__ void __launch_bounds__(128, 3)
attn_hmma_kernel() {
    extern __shared__ char smem[];
    uint32_t sb = s2u(smem);
    const int tid = threadIdx.x;
    const int w = tid >> 5, l = tid & 31;
    const int bx = blockIdx.x;
    const int bh = bx >> 7;
    const int qtile = (bx >> 1) & 63;
    const int half = bx & 1;
    const int qbase = qtile * BQ;
    const int kstart = half * (S_LEN / 2);

    const int lrow = (l & 7) + ((l & 8) ? 8 : 0);
    const int lch  = (l & 16) ? 1 : 0;

    load_q(sb, ((size_t)bh * S_LEN + qbase) * DHEAD, tid);
    load_kv(sb, 0, ((size_t)bh * S_LEN + kstart) * DHEAD, tid);
    CPA_COMMIT();
    CPA_WAIT0();
    __syncthreads();

    // Q fragments resident (hi and lo)
    uint32_t qh[4][4], ql[4][4];
    {
        const int qrow = w * 16 + lrow;
#pragma unroll
        for (int kb = 0; kb < 4; kb++) {
            uint32_t off = swz(qrow, kb * 2 + lch);
            ldsm4(qh[kb], sb + QH_OFF + off);
            ldsm4(ql[kb], sb + QL_OFF + off);
        }
    }

    float o[8][4];
#pragma unroll
    for (int nb = 0; nb < 8; nb++)
#pragma unroll
        for (int j = 0; j < 4; j++) o[nb][j] = 0.0f;
    float m0 = -1e30f, m1 = -1e30f, l0 = 0.0f, l1 = 0.0f;

    const uint32_t* mask_row0 =
        g_mask_bits + ((size_t)(qbase + w * 16 + (l >> 2))) * (S_LEN / 32) +
        (kstart >> 5);

    for (int t = 0; t < NTU; t++) {
        const int st = t & 1;
        const uint32_t kbuf = sb + STAGE_OFF(st);

        if (t + 1 < NTU)
            load_kv(sb, st ^ 1, ((size_t)bh * S_LEN + kstart + (t + 1) * BK) * DHEAD, tid);
        CPA_COMMIT();

        // ---- S = Q K^T : (qh + ql) x kh, 2 MMAs per position ----
        float s[8][4];
#pragma unroll
        for (int nb = 0; nb < 8; nb++)
#pragma unroll
            for (int j = 0; j < 4; j++) s[nb][j] = 0.0f;

#pragma unroll
        for (int kb = 0; kb < 4; kb++) {
#pragma unroll
            for (int nbp = 0; nbp < 4; nbp++) {
                uint32_t off = swz(nbp * 16 + lrow, kb * 2 + lch);
                uint32_t kh[4];
                ldsm4(kh, kbuf + KH_OFF + off);
                mma16816(s[nbp * 2],     qh[kb], kh[0], kh[2]);
                mma16816(s[nbp * 2],     ql[kb], kh[0], kh[2]);
                mma16816(s[nbp * 2 + 1], qh[kb], kh[1], kh[3]);
                mma16816(s[nbp * 2 + 1], ql[kb], kh[1], kh[3]);
            }
        }

        // ---- masked online softmax (rows warp-private) ----
        const uint2 ma = *(const uint2*)(mask_row0 + t * 2);
        const uint2 mb = *(const uint2*)(mask_row0 + 8 * (S_LEN / 32) + t * 2);
        const int j0 = (l & 3) * 2;
        float mx0 = -1e30f, mx1 = -1e30f;
#pragma unroll
        for (int nb = 0; nb < 8; nb++) {
            int c0 = nb * 8 + j0, c1 = c0 + 1;
            uint32_t wa0 = (c0 & 32) ? ma.y : ma.x;
            uint32_t wb0 = (c0 & 32) ? mb.y : mb.x;
            if (!((wa0 >> (c0 & 31)) & 1u)) s[nb][0] = -1e30f;
            if (!((wa0 >> (c1 & 31)) & 1u)) s[nb][1] = -1e30f;
            if (!((wb0 >> (c0 & 31)) & 1u)) s[nb][2] = -1e30f;
            if (!((wb0 >> (c1 & 31)) & 1u)) s[nb][3] = -1e30f;
            mx0 = fmaxf(mx0, fmaxf(s[nb][0], s[nb][1]));
            mx1 = fmaxf(mx1, fmaxf(s[nb][2], s[nb][3]));
        }
        mx0 = fmaxf(mx0, __shfl_xor_sync(0xffffffffu, mx0, 1));
        mx0 = fmaxf(mx0, __shfl_xor_sync(0xffffffffu, mx0, 2));
        mx1 = fmaxf(mx1, __shfl_xor_sync(0xffffffffu, mx1, 1));
        mx1 = fmaxf(mx1, __shfl_xor_sync(0xffffffffu, mx1, 2));
        float mn0 = fmaxf(m0, mx0), mn1 = fmaxf(m1, mx1);
        float al0 = ex2f(m0 - mn0), al1 = ex2f(m1 - mn1);
        m0 = mn0; m1 = mn1;

        float rs0 = 0.0f, rs1 = 0.0f;
        uint32_t p[4][4];
#pragma unroll
        for (int nb = 0; nb < 8; nb++) {
            float p0 = (s[nb][0] > -1e29f) ? ex2f(s[nb][0] - mn0) : 0.0f;
            float p1 = (s[nb][1] > -1e29f) ? ex2f(s[nb][1] - mn0) : 0.0f;
            float p2 = (s[nb][2] > -1e29f) ? ex2f(s[nb][2] - mn1) : 0.0f;
            float p3 = (s[nb][3] > -1e29f) ? ex2f(s[nb][3] - mn1) : 0.0f;
            rs0 += p0 + p1;
            rs1 += p2 + p3;
            __half2 h01 = __floats2half2_rn(p0, p1);
            __half2 h23 = __floats2half2_rn(p2, p3);
            int pk = nb >> 1, hi = nb & 1;
            // A-frag order: a0=(i,klow), a1=(i+8,klow), a2=(i,khigh), a3=(i+8,khigh)
            p[pk][hi * 2 + 0] = *(uint32_t*)&h01;
            p[pk][hi * 2 + 1] = *(uint32_t*)&h23;
        }
        rs0 += __shfl_xor_sync(0xffffffffu, rs0, 1);
        rs0 += __shfl_xor_sync(0xffffffffu, rs0, 2);
        rs1 += __shfl_xor_sync(0xffffffffu, rs1, 1);
        rs1 += __shfl_xor_sync(0xffffffffu, rs1, 2);
        l0 = l0 * al0 + rs0;
        l1 = l1 * al1 + rs1;

#pragma unroll
        for (int nb = 0; nb < 8; nb++) {
            o[nb][0] *= al0; o[nb][1] *= al0;
            o[nb][2] *= al1; o[nb][3] *= al1;
        }

        // ---- O += P (Vh + Vl), 2 MMAs per position ----
#pragma unroll
        for (int pk = 0; pk < 4; pk++) {
#pragma unroll
            for (int nbp = 0; nbp < 4; nbp++) {
                uint32_t off = swz(pk * 16 + lrow, nbp * 2 + lch);
                uint32_t vh[4], vl[4];
                ldsm4t(vh, kbuf + VH_OFF + off);
                ldsm4t(vl, kbuf + VL_OFF + off);
                mma16816(o[nbp * 2],     p[pk], vh[0], vh[1]);
                mma16816(o[nbp * 2],     p[pk], vl[0], vl[1]);
                mma16816(o[nbp * 2 + 1], p[pk], vh[2], vh[3]);
                mma16816(o[nbp * 2 + 1], p[pk], vl[2], vl[3]);
            }
        }

        CPA_WAIT0();
        __syncthreads();
    }

    // ---- epilogue: write unnormalized partial (U, m, l) ----
    const int r0g = qbase + w * 16 + (l >> 2);
    const size_t prow = (size_t)(bh * 2 + half) * S_LEN + r0g;
    float* up = g_U + prow * DHEAD + (l & 3) * 2;
#pragma unroll
    for (int nb = 0; nb < 8; nb++) {
        *(float2*)(up + nb * 8) = make_float2(o[nb][0], o[nb][1]);
        *(float2*)(up + 8 * DHEAD + nb * 8) = make_float2(o[nb][2], o[nb][3]);
    }
    if ((l & 3) == 0) {
        g_ml[prow] = make_float2(m0, l0);
        g_ml[prow + 8] = make_float2(m1, l1);
    }
}

// ---------------- merge kernel: combine the two kv-halves ----------------
__global__ void merge_kernel(float* __restrict__ Out) {
    size_t e = (size_t)blockIdx.x * 256 + threadIdx.x;   // float4 index
    int row_g = (int)(e >> 4);              // bh*4096 + row
    int d4 = ((int)e & 15) * 4;
    int bh = row_g >> 12, row = row_g & 4095;
    float2 mlA = g_ml[(size_t)(bh * 2 + 0) * S_LEN + row];
    float2 mlB = g_ml[(size_t)(bh * 2 + 1) * S_LEN + row];
    float m = fmaxf(mlA.x, mlB.x);
    float wA = ex2f(mlA.x - m), wB = ex2f(mlB.x - m);
    float lt = wA * mlA.y + wB * mlB.y;
    float inv = (lt > 0.0f) ? (1.0f / lt) : 0.0f;
    const float* ua = g_U + ((size_t)(bh * 2 + 0) * S_LEN + row) * DHEAD + d4;
    const float* ub = g_U + ((size_t)(bh * 2 + 1) * S_LEN + row) * DHEAD + d4;
    float4 a = *(const float4*)ua;
    float4 b = *(const float4*)ub;
    float4 r;
    r.x = (wA * a.x + wB * b.x) * inv;
    r.y = (wA * a.y + wB * b.y) * inv;
    r.z = (wA * a.z + wB * b.z) * inv;
    r.w = (wA * a.w + wB * b.w) * inv;
    *(float4*)(Out + (size_t)row_g * DHEAD + d4) = r;
}

// ---------------- launch ----------------
extern "C" void kernel_launch(void* const* d_in, const int* in_sizes, int n_in,
                              void* d_out, int out_size) {
    const float* Q = (const float*)d_in[0];
    const float* K = (const float*)d_in[1];
    const float* V = (const float*)d_in[2];
    const void* mask = d_in[4];
    float* Out = (float*)d_out;

    detect_mask_kernel<<<1, 32>>>((const uint32_t*)mask);
    pack_mask_kernel<<<(S_LEN * S_LEN) / 256, 256>>>(mask);
    split_kernel<<<(N_BH * S_LEN * DHEAD) / 256, 256>>>(Q, K, V);

    cudaFuncSetAttribute(attn_hmma_kernel, cudaFuncAttributeMaxDynamicSharedMemorySize,
                         SMEM_BYTES);
    attn_hmma_kernel<<<dim3(N_BH * 64 * 2), 128, SMEM_BYTES>>>();

    merge_kernel<<<(N_BH * S_LEN * DHEAD / 4) / 256, 256>>>(Out);
}

// round 5
// speedup vs baseline: 7.3949x; 1.4647x over previous
#include <cuda_runtime.h>
#include <cuda_fp16.h>
#include <cstdint>
#include <cstddef>

#define S_LEN 4096
#define DHEAD 64
#define N_BH  16
#define BQ    64
#define BK    64
#define NSPLIT 4
#define NTU   (S_LEN / BK / NSPLIT)     // 16 k-tiles per unit
// 1/sqrt(64) * log2(e)
#define SCALE_LOG2E 0.18033688011112042f

// ---------------- scratch (device globals; no runtime alloc) ----------------
__device__ __half g_qh[(size_t)N_BH * S_LEN * DHEAD];
__device__ __half g_kh[(size_t)N_BH * S_LEN * DHEAD];
__device__ __half g_vh[(size_t)N_BH * S_LEN * DHEAD];
__device__ float  g_U[(size_t)N_BH * NSPLIT * S_LEN * DHEAD];  // unnormalized partials
__device__ float2 g_ml[(size_t)N_BH * NSPLIT * S_LEN];         // (m, l) per partial row
__device__ uint32_t g_mask_bits[(S_LEN * S_LEN) / 32];
__device__ int g_mask_wide;

// ---------------- smem layout (bytes) ----------------
// Qh[64x64 fp16 = 8KB], 2 stages of {Kh 8KB, Vh 8KB}.
#define QH_OFF 0
#define STAGE_OFF(s) (8192 + (s) * 16384)
#define KH_OFF 0
#define VH_OFF 8192
#define SMEM_BYTES 40960

// swizzled byte offset of (row, 16B-chunk) in a 128B-row tile
__device__ __forceinline__ uint32_t swz(int row, int chunk) {
    return (uint32_t)(row * 128 + ((chunk ^ (row & 7)) << 4));
}

// ---------------- PTX helpers ----------------
__device__ __forceinline__ uint32_t s2u(const void* p) {
    uint32_t a;
    asm("{ .reg .u64 t; cvta.to.shared.u64 t, %1; cvt.u32.u64 %0, t; }" : "=r"(a) : "l"(p));
    return a;
}
__device__ __forceinline__ float ex2f(float x) {
    float y;
    asm("ex2.approx.ftz.f32 %0, %1;" : "=f"(y) : "f"(x));
    return y;
}
__device__ __forceinline__ void ldsm4(uint32_t* r, uint32_t addr) {
    asm volatile("ldmatrix.sync.aligned.m8n8.x4.shared.b16 {%0, %1, %2, %3}, [%4];"
                 : "=r"(r[0]), "=r"(r[1]), "=r"(r[2]), "=r"(r[3]) : "r"(addr));
}
__device__ __forceinline__ void ldsm4t(uint32_t* r, uint32_t addr) {
    asm volatile("ldmatrix.sync.aligned.m8n8.x4.trans.shared.b16 {%0, %1, %2, %3}, [%4];"
                 : "=r"(r[0]), "=r"(r[1]), "=r"(r[2]), "=r"(r[3]) : "r"(addr));
}
__device__ __forceinline__ void mma16816(float* d, const uint32_t* a, uint32_t b0, uint32_t b1) {
    asm volatile("mma.sync.aligned.m16n8k16.row.col.f32.f16.f16.f32 "
                 "{%0, %1, %2, %3}, {%4, %5, %6, %7}, {%8, %9}, {%0, %1, %2, %3};"
                 : "+f"(d[0]), "+f"(d[1]), "+f"(d[2]), "+f"(d[3])
                 : "r"(a[0]), "r"(a[1]), "r"(a[2]), "r"(a[3]), "r"(b0), "r"(b1));
}
__device__ __forceinline__ void cpa16(uint32_t dst, const void* src) {
    asm volatile("cp.async.cg.shared.global [%0], [%1], 16;" :: "r"(dst), "l"(src));
}
#define CPA_COMMIT() asm volatile("cp.async.commit_group;" ::: "memory")
#define CPA_WAIT0()  asm volatile("cp.async.wait_group 0;" ::: "memory")

// ---------------- preprocess kernels ----------------
__global__ void detect_mask_kernel(const uint32_t* __restrict__ m) {
    bool wide = true;
#pragma unroll
    for (int i = 0; i < 4; i++) {
        uint32_t w = m[threadIdx.x + i * 256];
        if (w != 0u && w != 1u && w != 0x3F800000u) wide = false;
    }
    int allw = __syncthreads_and(wide ? 1 : 0);
    if (threadIdx.x == 0) g_mask_wide = allw;
}

__global__ void pack_mask_kernel(const void* __restrict__ mask) {
    int idx = blockIdx.x * blockDim.x + threadIdx.x;
    bool v;
    if (g_mask_wide) v = (((const uint32_t*)mask)[idx] != 0u);
    else             v = (((const uint8_t*)mask)[idx] != 0);
    uint32_t bits = __ballot_sync(0xffffffffu, v);
    if ((threadIdx.x & 31) == 0) g_mask_bits[idx >> 5] = bits;
}

__global__ void split_kernel(const float* __restrict__ Q, const float* __restrict__ K,
                             const float* __restrict__ V) {
    size_t idx = (size_t)blockIdx.x * 256 + threadIdx.x;
    g_qh[idx] = __float2half_rn(Q[idx] * SCALE_LOG2E);
    g_kh[idx] = __float2half_rn(K[idx]);
    g_vh[idx] = __float2half_rn(V[idx]);
}

// ---------------- tile loaders ----------------
__device__ __forceinline__ void load_kv(uint32_t sb, int stage, size_t ebase, int tid) {
    uint32_t base = sb + STAGE_OFF(stage);
#pragma unroll
    for (int it = 0; it < 4; it++) {
        int cid = it * 128 + tid;            // 0..511 chunks, 64 rows x 8 chunks
        int row = cid >> 3, c = cid & 7;
        uint32_t off = swz(row, c);
        size_t src = ebase + (size_t)row * DHEAD + c * 8;
        cpa16(base + KH_OFF + off, g_kh + src);
        cpa16(base + VH_OFF + off, g_vh + src);
    }
}
__device__ __forceinline__ void load_q(uint32_t sb, size_t ebase, int tid) {
#pragma unroll
    for (int it = 0; it < 4; it++) {
        int cid = it * 128 + tid;
        int row = cid >> 3, c = cid & 7;
        uint32_t off = swz(row, c);
        size_t src = ebase + (size_t)row * DHEAD + c * 8;
        cpa16(sb + QH_OFF + off, g_qh + src);
    }
}

// ---------------- main attention kernel ----------------
// Unit = (bh, qtile of 64 rows, kv-quarter of 1024 keys). 128 threads, 4 warps,
// each warp owns 16 q-rows x all 64 keys of the tile.
__global__ void __launch_bounds__(128, 4)
attn_hmma_kernel() {
    extern __shared__ char smem[];
    uint32_t sb = s2u(smem);
    const int tid = threadIdx.x;
    const int w = tid >> 5, l = tid & 31;
    const int bx = blockIdx.x;
    const int bh = bx >> 8;
    const int qtile = (bx >> 2) & 63;
    const int split = bx & 3;
    const int qbase = qtile * BQ;
    const int kstart = split * (S_LEN / NSPLIT);

    const int lrow = (l & 7) + ((l & 8) ? 8 : 0);
    const int lch  = (l & 16) ? 1 : 0;

    load_q(sb, ((size_t)bh * S_LEN + qbase) * DHEAD, tid);
    load_kv(sb, 0, ((size_t)bh * S_LEN + kstart) * DHEAD, tid);
    CPA_COMMIT();
    CPA_WAIT0();
    __syncthreads();

    // Q fragments resident
    uint32_t qh[4][4];
    {
        const int qrow = w * 16 + lrow;
#pragma unroll
        for (int kb = 0; kb < 4; kb++)
            ldsm4(qh[kb], sb + QH_OFF + swz(qrow, kb * 2 + lch));
    }

    float o[8][4];
#pragma unroll
    for (int nb = 0; nb < 8; nb++)
#pragma unroll
        for (int j = 0; j < 4; j++) o[nb][j] = 0.0f;
    float m0 = -1e30f, m1 = -1e30f, l0 = 0.0f, l1 = 0.0f;

    const uint32_t* mask_row0 =
        g_mask_bits + ((size_t)(qbase + w * 16 + (l >> 2))) * (S_LEN / 32) +
        (kstart >> 5);

    for (int t = 0; t < NTU; t++) {
        const int st = t & 1;
        const uint32_t kbuf = sb + STAGE_OFF(st);

        if (t + 1 < NTU)
            load_kv(sb, st ^ 1, ((size_t)bh * S_LEN + kstart + (t + 1) * BK) * DHEAD, tid);
        CPA_COMMIT();

        // ---- init S accumulators with additive mask bias (0 or -1e30) ----
        const uint2 ma = *(const uint2*)(mask_row0 + t * 2);
        const uint2 mb = *(const uint2*)(mask_row0 + 8 * (S_LEN / 32) + t * 2);
        const int j0 = (l & 3) * 2;
        float s[8][4];
#pragma unroll
        for (int nb = 0; nb < 8; nb++) {
            int c0 = nb * 8 + j0, c1 = c0 + 1;
            uint32_t wa0 = (c0 & 32) ? ma.y : ma.x;
            uint32_t wb0 = (c0 & 32) ? mb.y : mb.x;
            s[nb][0] = ((wa0 >> (c0 & 31)) & 1u) ? 0.0f : -1e30f;
            s[nb][1] = ((wa0 >> (c1 & 31)) & 1u) ? 0.0f : -1e30f;
            s[nb][2] = ((wb0 >> (c0 & 31)) & 1u) ? 0.0f : -1e30f;
            s[nb][3] = ((wb0 >> (c1 & 31)) & 1u) ? 0.0f : -1e30f;
        }

        // ---- S += Q K^T (single fp16 term) ----
#pragma unroll
        for (int kb = 0; kb < 4; kb++) {
#pragma unroll
            for (int nbp = 0; nbp < 4; nbp++) {
                uint32_t off = swz(nbp * 16 + lrow, kb * 2 + lch);
                uint32_t kh[4];
                ldsm4(kh, kbuf + KH_OFF + off);
                mma16816(s[nbp * 2],     qh[kb], kh[0], kh[2]);
                mma16816(s[nbp * 2 + 1], qh[kb], kh[1], kh[3]);
            }
        }

        // ---- online softmax (rows warp-private; masked p underflows to 0) ----
        float mx0 = -1e30f, mx1 = -1e30f;
#pragma unroll
        for (int nb = 0; nb < 8; nb++) {
            mx0 = fmaxf(mx0, fmaxf(s[nb][0], s[nb][1]));
            mx1 = fmaxf(mx1, fmaxf(s[nb][2], s[nb][3]));
        }
        mx0 = fmaxf(mx0, __shfl_xor_sync(0xffffffffu, mx0, 1));
        mx0 = fmaxf(mx0, __shfl_xor_sync(0xffffffffu, mx0, 2));
        mx1 = fmaxf(mx1, __shfl_xor_sync(0xffffffffu, mx1, 1));
        mx1 = fmaxf(mx1, __shfl_xor_sync(0xffffffffu, mx1, 2));
        float mn0 = fmaxf(m0, mx0), mn1 = fmaxf(m1, mx1);
        float al0 = ex2f(m0 - mn0), al1 = ex2f(m1 - mn1);
        m0 = mn0; m1 = mn1;

        float rs0 = 0.0f, rs1 = 0.0f;
        uint32_t p[4][4];
#pragma unroll
        for (int nb = 0; nb < 8; nb++) {
            float p0 = ex2f(s[nb][0] - mn0);
            float p1 = ex2f(s[nb][1] - mn0);
            float p2 = ex2f(s[nb][2] - mn1);
            float p3 = ex2f(s[nb][3] - mn1);
            rs0 += p0 + p1;
            rs1 += p2 + p3;
            __half2 h01 = __floats2half2_rn(p0, p1);
            __half2 h23 = __floats2half2_rn(p2, p3);
            int pk = nb >> 1, hi = nb & 1;
            // A-frag order: a0=(i,klow), a1=(i+8,klow), a2=(i,khigh), a3=(i+8,khigh)
            p[pk][hi * 2 + 0] = *(uint32_t*)&h01;
            p[pk][hi * 2 + 1] = *(uint32_t*)&h23;
        }
        rs0 += __shfl_xor_sync(0xffffffffu, rs0, 1);
        rs0 += __shfl_xor_sync(0xffffffffu, rs0, 2);
        rs1 += __shfl_xor_sync(0xffffffffu, rs1, 1);
        rs1 += __shfl_xor_sync(0xffffffffu, rs1, 2);
        l0 = l0 * al0 + rs0;
        l1 = l1 * al1 + rs1;

#pragma unroll
        for (int nb = 0; nb < 8; nb++) {
            o[nb][0] *= al0; o[nb][1] *= al0;
            o[nb][2] *= al1; o[nb][3] *= al1;
        }

        // ---- O += P V (single fp16 term) ----
#pragma unroll
        for (int pk = 0; pk < 4; pk++) {
#pragma unroll
            for (int nbp = 0; nbp < 4; nbp++) {
                uint32_t off = swz(pk * 16 + lrow, nbp * 2 + lch);
                uint32_t vh[4];
                ldsm4t(vh, kbuf + VH_OFF + off);
                mma16816(o[nbp * 2],     p[pk], vh[0], vh[1]);
                mma16816(o[nbp * 2 + 1], p[pk], vh[2], vh[3]);
            }
        }

        CPA_WAIT0();
        __syncthreads();
    }

    // ---- epilogue: write unnormalized partial (U, m, l) ----
    const int r0g = qbase + w * 16 + (l >> 2);
    const size_t prow = (size_t)(bh * NSPLIT + split) * S_LEN + r0g;
    float* up = g_U + prow * DHEAD + (l & 3) * 2;
#pragma unroll
    for (int nb = 0; nb < 8; nb++) {
        *(float2*)(up + nb * 8) = make_float2(o[nb][0], o[nb][1]);
        *(float2*)(up + 8 * DHEAD + nb * 8) = make_float2(o[nb][2], o[nb][3]);
    }
    if ((l & 3) == 0) {
        g_ml[prow] = make_float2(m0, l0);
        g_ml[prow + 8] = make_float2(m1, l1);
    }
}

// ---------------- merge kernel: combine the NSPLIT kv-partials ----------------
__global__ void merge_kernel(float* __restrict__ Out) {
    size_t e = (size_t)blockIdx.x * 256 + threadIdx.x;   // float4 index
    int row_g = (int)(e >> 4);              // bh*4096 + row
    int d4 = ((int)e & 15) * 4;
    int bh = row_g >> 12, row = row_g & 4095;

    float2 ml[NSPLIT];
    float m = -1e30f;
#pragma unroll
    for (int sp = 0; sp < NSPLIT; sp++) {
        ml[sp] = g_ml[(size_t)(bh * NSPLIT + sp) * S_LEN + row];
        m = fmaxf(m, ml[sp].x);
    }
    float wt[NSPLIT], lt = 0.0f;
#pragma unroll
    for (int sp = 0; sp < NSPLIT; sp++) {
        wt[sp] = ex2f(ml[sp].x - m);
        lt += wt[sp] * ml[sp].y;
    }
    float inv = (lt > 0.0f) ? (1.0f / lt) : 0.0f;
    float4 r = make_float4(0.0f, 0.0f, 0.0f, 0.0f);
#pragma unroll
    for (int sp = 0; sp < NSPLIT; sp++) {
        const float* u = g_U + ((size_t)(bh * NSPLIT + sp) * S_LEN + row) * DHEAD + d4;
        float4 a = *(const float4*)u;
        r.x += wt[sp] * a.x; r.y += wt[sp] * a.y;
        r.z += wt[sp] * a.z; r.w += wt[sp] * a.w;
    }
    r.x *= inv; r.y *= inv; r.z *= inv; r.w *= inv;
    *(float4*)(Out + (size_t)row_g * DHEAD + d4) = r;
}

// ---------------- launch ----------------
extern "C" void kernel_launch(void* const* d_in, const int* in_sizes, int n_in,
                              void* d_out, int out_size) {
    const float* Q = (const float*)d_in[0];
    const float* K = (const float*)d_in[1];
    const float* V = (const float*)d_in[2];
    const void* mask = d_in[4];
    float* Out = (float*)d_out;

    detect_mask_kernel<<<1, 256>>>((const uint32_t*)mask);
    pack_mask_kernel<<<(S_LEN * S_LEN) / 256, 256>>>(mask);
    split_kernel<<<(N_BH * S_LEN * DHEAD) / 256, 256>>>(Q, K, V);

    cudaFuncSetAttribute(attn_hmma_kernel, cudaFuncAttributeMaxDynamicSharedMemorySize,
                         SMEM_BYTES);
    attn_hmma_kernel<<<dim3(N_BH * 64 * NSPLIT), 128, SMEM_BYTES>>>();

    merge_kernel<<<(N_BH * S_LEN * DHEAD / 4) / 256, 256>>>(Out);
}